// round 1
// baseline (speedup 1.0000x reference)
#include <cuda_runtime.h>
#include <math.h>

#define Bn   4
#define Sn   2048
#define DMn  512
#define Hn   8
#define DKn  64
#define MROWS (Bn * Sn)   // 8192

// Scratch (device globals: allocation-free per harness rules)
__device__ float g_q[Bn * Hn * Sn * DKn];
__device__ float g_k[Bn * Hn * Sn * DKn];
__device__ float g_v[Bn * Hn * Sn * DKn];
__device__ float g_x[Bn * Sn * DMn];

// ---------------------------------------------------------------------------
// GEMM: Y = A @ W^T + bias.  A: [M, 512] row-major, W: [N, 512] row-major.
// head_layout=1 -> scatter Y[m, n] into [B, H, S, DK] (n = h*64 + d).
// 64x64 block tile, K-step 16, 256 threads, 4x4 register micro-tile.
// Smem tiles stored K-major-transposed so the inner loop is 2x LDS.128 + 16 FFMA.
// ---------------------------------------------------------------------------
__global__ void __launch_bounds__(256) gemm_kernel(
    const float* __restrict__ A, const float* __restrict__ W,
    const float* __restrict__ bias, float* __restrict__ Y, int head_layout)
{
    __shared__ float As[16][64];
    __shared__ float Ws[16][64];
    const int t  = threadIdx.x;
    const int tx = t & 15, ty = t >> 4;
    const int m0 = blockIdx.x * 64, n0 = blockIdx.y * 64;

    float acc[4][4] = {};

    for (int k0 = 0; k0 < DMn; k0 += 16) {
        const int r = t >> 2;          // 0..63
        const int c = (t & 3) * 4;     // 0,4,8,12
        float4 av = *(const float4*)&A[(size_t)(m0 + r) * DMn + k0 + c];
        As[c + 0][r] = av.x; As[c + 1][r] = av.y;
        As[c + 2][r] = av.z; As[c + 3][r] = av.w;
        float4 wv = *(const float4*)&W[(size_t)(n0 + r) * DMn + k0 + c];
        Ws[c + 0][r] = wv.x; Ws[c + 1][r] = wv.y;
        Ws[c + 2][r] = wv.z; Ws[c + 3][r] = wv.w;
        __syncthreads();

        #pragma unroll
        for (int kk = 0; kk < 16; kk++) {
            float a[4], w[4];
            *(float4*)a = *(const float4*)&As[kk][ty * 4];
            *(float4*)w = *(const float4*)&Ws[kk][tx * 4];
            #pragma unroll
            for (int i = 0; i < 4; i++)
                #pragma unroll
                for (int j = 0; j < 4; j++)
                    acc[i][j] = fmaf(a[i], w[j], acc[i][j]);
        }
        __syncthreads();
    }

    #pragma unroll
    for (int i = 0; i < 4; i++) {
        const int m = m0 + ty * 4 + i;
        #pragma unroll
        for (int j = 0; j < 4; j++) {
            const int n = n0 + tx * 4 + j;
            const float v = acc[i][j] + bias[n];
            if (head_layout) {
                const int b = m >> 11, s = m & 2047;
                const int h = n >> 6,  d = n & 63;
                g_dummy_guard:
                Y[(((size_t)(b * Hn + h)) * Sn + s) * DKn + d] = v;
            } else {
                Y[(size_t)m * DMn + n] = v;
            }
        }
    }
}

// ---------------------------------------------------------------------------
// Flash attention over projected Q/K/V in [B,H,S,DK] layout.
// Block = 64 query rows; loop over 32 key tiles of 64.
// Smem: Qs (straight), KP (K transposed, reused as P tile), Vs (straight).
// 256 threads as 16x16, 4x4 micro-tiles, shfl width-16 row reductions.
// Output written to g_x in [B, S, H*DK] layout.
// ---------------------------------------------------------------------------
__global__ void __launch_bounds__(256) attn_kernel(
    const float* __restrict__ Q, const float* __restrict__ K,
    const float* __restrict__ V, const int* __restrict__ mask,
    float* __restrict__ X)
{
    __shared__ float Qs[64 * 64];
    __shared__ float KP[64 * 64];
    __shared__ float Vs[64 * 64];

    const int t  = threadIdx.x;
    const int tx = t & 15, ty = t >> 4;
    const int qt = blockIdx.x, h = blockIdx.y, b = blockIdx.z;
    const int q0 = qt * 64;
    const float SCALE = 0.125f;   // 1/sqrt(64)

    const size_t head_off = (size_t)(b * Hn + h) * Sn * DKn;
    const float* Qbase = Q + head_off + (size_t)q0 * DKn;
    const float* Kbase = K + head_off;
    const float* Vbase = V + head_off;

    // Load Q tile (straight layout; reads are broadcast-class -> conflict-free)
    {
        const int r = t >> 4, c = (t & 15) * 4;
        #pragma unroll
        for (int rr = 0; rr < 64; rr += 16) {
            float4 vq = *(const float4*)&Qbase[(size_t)(rr + r) * DKn + c];
            *(float4*)&Qs[(rr + r) * 64 + c] = vq;
        }
    }

    float Oacc[4][4] = {};
    float mrow[4], lrow[4];
    #pragma unroll
    for (int i = 0; i < 4; i++) { mrow[i] = -INFINITY; lrow[i] = 0.0f; }

    for (int kt = 0; kt < Sn / 64; kt++) {
        const int k0 = kt * 64;
        __syncthreads();   // previous PV done reading KP/Vs (also covers Q load, iter 0)

        // Load K transposed (KP[d][kc]) and V straight
        {
            const int r = t >> 4, c = (t & 15) * 4;
            #pragma unroll
            for (int rr = 0; rr < 64; rr += 16) {
                const int row = rr + r;
                float4 kv = *(const float4*)&Kbase[(size_t)(k0 + row) * DKn + c];
                KP[(c + 0) * 64 + row] = kv.x;
                KP[(c + 1) * 64 + row] = kv.y;
                KP[(c + 2) * 64 + row] = kv.z;
                KP[(c + 3) * 64 + row] = kv.w;
                float4 vv = *(const float4*)&Vbase[(size_t)(k0 + row) * DKn + c];
                *(float4*)&Vs[row * 64 + c] = vv;
            }
        }
        __syncthreads();

        // S = Q @ K^T for this 64x64 tile (4x4 per thread)
        float s[4][4] = {};
        #pragma unroll
        for (int d = 0; d < 64; d += 4) {
            float a[4][4], bb[4][4];
            #pragma unroll
            for (int i = 0; i < 4; i++)
                *(float4*)a[i] = *(const float4*)&Qs[(ty * 4 + i) * 64 + d];
            #pragma unroll
            for (int dd = 0; dd < 4; dd++)
                *(float4*)bb[dd] = *(const float4*)&KP[(d + dd) * 64 + tx * 4];
            #pragma unroll
            for (int i = 0; i < 4; i++)
                #pragma unroll
                for (int j = 0; j < 4; j++)
                    #pragma unroll
                    for (int dd = 0; dd < 4; dd++)
                        s[i][j] = fmaf(a[i][dd], bb[dd][j], s[i][j]);
        }
        __syncthreads();   // everyone done reading KP before it becomes the P tile

        // Scale + mask + online softmax; write P into KP
        #pragma unroll
        for (int i = 0; i < 4; i++) {
            const int qg = q0 + ty * 4 + i;
            const int4 mk = *(const int4*)&mask[((size_t)b * Sn + qg) * Sn + k0 + tx * 4];
            s[i][0] = mk.x ? s[i][0] * SCALE : -1e9f;
            s[i][1] = mk.y ? s[i][1] * SCALE : -1e9f;
            s[i][2] = mk.z ? s[i][2] * SCALE : -1e9f;
            s[i][3] = mk.w ? s[i][3] * SCALE : -1e9f;

            float mx = fmaxf(fmaxf(s[i][0], s[i][1]), fmaxf(s[i][2], s[i][3]));
            #pragma unroll
            for (int off = 8; off >= 1; off >>= 1)
                mx = fmaxf(mx, __shfl_xor_sync(0xffffffffu, mx, off, 16));

            const float mnew = fmaxf(mrow[i], mx);
            const float corr = __expf(mrow[i] - mnew);
            float p0 = __expf(s[i][0] - mnew);
            float p1 = __expf(s[i][1] - mnew);
            float p2 = __expf(s[i][2] - mnew);
            float p3 = __expf(s[i][3] - mnew);
            float rs = p0 + p1 + p2 + p3;
            #pragma unroll
            for (int off = 8; off >= 1; off >>= 1)
                rs += __shfl_xor_sync(0xffffffffu, rs, off, 16);

            lrow[i] = lrow[i] * corr + rs;
            mrow[i] = mnew;
            #pragma unroll
            for (int j = 0; j < 4; j++) Oacc[i][j] *= corr;

            float4 pv = make_float4(p0, p1, p2, p3);
            *(float4*)&KP[(ty * 4 + i) * 64 + tx * 4] = pv;
        }
        __syncthreads();   // P visible to all

        // O += P @ V
        #pragma unroll
        for (int kc = 0; kc < 64; kc++) {
            const float4 vv = *(const float4*)&Vs[kc * 64 + tx * 4];
            #pragma unroll
            for (int i = 0; i < 4; i++) {
                const float p = KP[(ty * 4 + i) * 64 + kc];
                Oacc[i][0] = fmaf(p, vv.x, Oacc[i][0]);
                Oacc[i][1] = fmaf(p, vv.y, Oacc[i][1]);
                Oacc[i][2] = fmaf(p, vv.z, Oacc[i][2]);
                Oacc[i][3] = fmaf(p, vv.w, Oacc[i][3]);
            }
        }
    }

    // Normalize and write to [B, S, H*DK]
    #pragma unroll
    for (int i = 0; i < 4; i++) {
        const float inv = 1.0f / lrow[i];
        const int qg = q0 + ty * 4 + i;
        float4 o = make_float4(Oacc[i][0] * inv, Oacc[i][1] * inv,
                               Oacc[i][2] * inv, Oacc[i][3] * inv);
        *(float4*)&X[((size_t)b * Sn + qg) * DMn + h * DKn + tx * 4] = o;
    }
}

extern "C" void kernel_launch(void* const* d_in, const int* in_sizes, int n_in,
                              void* d_out, int out_size)
{
    const float* query = (const float*)d_in[0];
    const float* key   = (const float*)d_in[1];
    const float* value = (const float*)d_in[2];
    const int*   mask  = (const int*)  d_in[3];
    const float* Wq = (const float*)d_in[4];
    const float* bq = (const float*)d_in[5];
    const float* Wk = (const float*)d_in[6];
    const float* bk = (const float*)d_in[7];
    const float* Wv = (const float*)d_in[8];
    const float* bv = (const float*)d_in[9];
    const float* Wo = (const float*)d_in[10];
    const float* bo = (const float*)d_in[11];
    float* out = (float*)d_out;

    float *qp, *kp, *vp, *xp;
    cudaGetSymbolAddress((void**)&qp, g_q);
    cudaGetSymbolAddress((void**)&kp, g_k);
    cudaGetSymbolAddress((void**)&vp, g_v);
    cudaGetSymbolAddress((void**)&xp, g_x);

    dim3 gg(MROWS / 64, DMn / 64);   // 128 x 8
    gemm_kernel<<<gg, 256>>>(query, Wq, bq, qp, 1);
    gemm_kernel<<<gg, 256>>>(key,   Wk, bk, kp, 1);
    gemm_kernel<<<gg, 256>>>(value, Wv, bv, vp, 1);

    dim3 ag(Sn / 64, Hn, Bn);        // 32 x 8 x 4
    attn_kernel<<<ag, 256>>>(qp, kp, vp, mask, xp);

    gemm_kernel<<<gg, 256>>>(xp, Wo, bo, out, 0);
}

// round 5
// speedup vs baseline: 2.0074x; 2.0074x over previous
#include <cuda_runtime.h>
#include <cstdint>
#include <math.h>

#define Bn 4
#define Sn 2048
#define DMn 512
#define Hn 8
#define DKn 64
#define BHn (Bn * Hn)             // 32
#define MROWS (Bn * Sn)           // 8192
#define K3n (3 * DMn)             // 1536
#define D3n (3 * DKn)             // 192

typedef unsigned short u16;
typedef unsigned int u32;

// ---------------- scratch (device globals; allocation-free) ----------------
__device__ u16 g_in3[3][MROWS * K3n];        // query/key/value, A-pattern triples
__device__ u16 g_w3[4][DMn * K3n];           // Wq/Wk/Wv/Wo, B-pattern triples
__device__ u16 g_q3[BHn * Sn * D3n];         // Q proj, A-pattern  [bh][s][192]
__device__ u16 g_k3[BHn * Sn * D3n];         // K proj, B-pattern  [bh][s][192]
__device__ u16 g_vhi[BHn * Sn * DKn];        // V proj hi plane    [bh][s][64]
__device__ u16 g_vlo[BHn * Sn * DKn];        // V proj lo plane
__device__ u16 g_x3[MROWS * K3n];            // attn out, A-pattern [m][1536]

// ---------------- helpers ----------------
__device__ __forceinline__ u16 bf16b(float v) {
    u32 u = __float_as_uint(v);
    u += 0x7FFFu + ((u >> 16) & 1u);
    return (u16)(u >> 16);
}
__device__ __forceinline__ void split2(float v, u16& h, u16& l) {
    h = bf16b(v);
    l = bf16b(v - __uint_as_float((u32)h << 16));
}
__device__ __forceinline__ u32 pk(u16 lo, u16 hi) { return (u32)lo | ((u32)hi << 16); }

__device__ __forceinline__ void mma16816(float* c, const u32* a, const u32* b) {
    asm volatile(
        "mma.sync.aligned.m16n8k16.row.col.f32.bf16.bf16.f32 "
        "{%0,%1,%2,%3},{%4,%5,%6,%7},{%8,%9},{%0,%1,%2,%3};"
        : "+f"(c[0]), "+f"(c[1]), "+f"(c[2]), "+f"(c[3])
        : "r"(a[0]), "r"(a[1]), "r"(a[2]), "r"(a[3]), "r"(b[0]), "r"(b[1]));
}
__device__ __forceinline__ void ldm_x2_trans(u32& r0, u32& r1, u32 addr) {
    asm volatile("ldmatrix.sync.aligned.m8n8.x2.trans.shared.b16 {%0,%1}, [%2];"
                 : "=r"(r0), "=r"(r1) : "r"(addr));
}
__device__ __forceinline__ u32 smem_u32(const void* p) {
    u32 a;
    asm("{ .reg .u64 t; cvta.to.shared.u64 t, %1; cvt.u32.u64 %0, t; }" : "=r"(a) : "l"(p));
    return a;
}
__device__ __forceinline__ void cpa16(u32 dst, const void* src) {
    asm volatile("cp.async.cg.shared.global [%0], [%1], 16;" :: "r"(dst), "l"(src));
}
#define CP_COMMIT() asm volatile("cp.async.commit_group;" ::: "memory")
#define CP_WAIT1() asm volatile("cp.async.wait_group 1;" ::: "memory")
#define CP_WAIT0() asm volatile("cp.async.wait_group 0;" ::: "memory")

__device__ __forceinline__ void writeA3(u16* p, float v0, float v1) {
    u16 h0, l0, h1, l1; split2(v0, h0, l0); split2(v1, h1, l1);
    u32* q = (u32*)p;
    q[0] = pk(h0, h0); q[1] = pk(l0, h1); q[2] = pk(h1, l1);
}
__device__ __forceinline__ void writeB3(u16* p, float v0, float v1) {
    u16 h0, l0, h1, l1; split2(v0, h0, l0); split2(v1, h1, l1);
    u32* q = (u32*)p;
    q[0] = pk(h0, l0); q[1] = pk(h0, h1); q[2] = pk(l1, h1);
}

// ---------------- convert: fp32 [rows][512] -> bf16 triple [rows][1536] ----------------
__global__ void __launch_bounds__(256) convert_kernel(
    const float* __restrict__ src, u16* __restrict__ dst, int rows, int bpat)
{
    const int n = rows * 256;   // pairs of k
    for (int i = blockIdx.x * 256 + threadIdx.x; i < n; i += gridDim.x * 256) {
        const int m = i >> 8, kp = i & 255;
        const float2 v = *(const float2*)(src + (size_t)m * DMn + kp * 2);
        u16* p = dst + (size_t)m * K3n + kp * 6;
        if (bpat) writeB3(p, v.x, v.y);
        else      writeA3(p, v.x, v.y);
    }
}

// ---------------- warp-MMA GEMM: C = A3 @ W3^T + bias ----------------
// A3 [8192][1536], W3 [512][1536] (both bf16 triple). CTA 128x128, K-step 32,
// 256 thr (8 warps, 4x2), warp tile 32x64, double-buffered cp.async.
// mode 0: fp32 out[m][512]   mode 1: Q3 A-pattern [bh][s][192]
// mode 2: K3 B-pattern       mode 3: Vhi/Vlo planes [bh][s][64]
__global__ void __launch_bounds__(256) gemm_mma_kernel(
    const u16* __restrict__ A3, const u16* __restrict__ W3,
    const float* __restrict__ bias, int mode, float* __restrict__ outF,
    u16* __restrict__ d0, u16* __restrict__ d1)
{
    extern __shared__ char smem[];
    const u32 sbase = smem_u32(smem);
    const int tid = threadIdx.x, w = tid >> 5, lane = tid & 31;
    const int wm = w >> 1, wn = w & 1;
    const int qd = lane >> 2, qc = lane & 3;
    const int m0 = blockIdx.x * 128, n0 = blockIdx.y * 128;
    // stage: A rows 128 x 80B (64B data+16 pad), B same; stage size 20480

    float acc[2][8][4];
    #pragma unroll
    for (int i = 0; i < 2; i++)
        #pragma unroll
        for (int j = 0; j < 8; j++)
            #pragma unroll
            for (int k = 0; k < 4; k++) acc[i][j][k] = 0.0f;

    auto issue = [&](int stage, int k0) {
        #pragma unroll
        for (int i = 0; i < 4; i++) {
            const int c = tid + i * 256;          // 0..1023
            const int isB = c >> 9;
            const int cc = c & 511;
            const int row = cc >> 2, col = cc & 3;
            const u32 dst = sbase + stage * 20480 + isB * 10240 + row * 80 + col * 16;
            const u16* src = isB ? (W3 + (size_t)(n0 + row) * K3n + k0 + col * 8)
                                 : (A3 + (size_t)(m0 + row) * K3n + k0 + col * 8);
            cpa16(dst, src);
        }
        CP_COMMIT();
    };

    issue(0, 0);
    int buf = 0;
    for (int it = 0; it < 48; it++) {
        if (it + 1 < 48) { issue(buf ^ 1, (it + 1) * 32); CP_WAIT1(); }
        else             { CP_WAIT0(); }
        __syncthreads();
        const char* As = smem + buf * 20480;
        const char* Bs = As + 10240;
        #pragma unroll
        for (int j = 0; j < 2; j++) {
            u32 a[2][4];
            #pragma unroll
            for (int fm = 0; fm < 2; fm++) {
                const char* p = As + (wm * 32 + fm * 16 + qd) * 80 + j * 32 + qc * 4;
                a[fm][0] = *(const u32*)p;
                a[fm][1] = *(const u32*)(p + 8 * 80);
                a[fm][2] = *(const u32*)(p + 16);
                a[fm][3] = *(const u32*)(p + 8 * 80 + 16);
            }
            #pragma unroll
            for (int fn = 0; fn < 8; fn++) {
                const char* q = Bs + (wn * 64 + fn * 8 + qd) * 80 + j * 32 + qc * 4;
                u32 b[2] = { *(const u32*)q, *(const u32*)(q + 16) };
                mma16816(acc[0][fn], a[0], b);
                mma16816(acc[1][fn], a[1], b);
            }
        }
        __syncthreads();
        buf ^= 1;
    }

    // epilogue
    #pragma unroll
    for (int fm = 0; fm < 2; fm++) {
        #pragma unroll
        for (int fn = 0; fn < 8; fn++) {
            const int mbase = m0 + wm * 32 + fm * 16 + qd;
            const int n = n0 + wn * 64 + fn * 8 + qc * 2;
            const float b0 = bias[n], b1 = bias[n + 1];
            #pragma unroll
            for (int half = 0; half < 2; half++) {
                const int m = mbase + half * 8;
                const float v0 = acc[fm][fn][half * 2 + 0] + b0;
                const float v1 = acc[fm][fn][half * 2 + 1] + b1;
                if (mode == 0) {
                    *(float2*)(outF + (size_t)m * DMn + n) = make_float2(v0, v1);
                } else {
                    const int bb = m >> 11, s = m & 2047;
                    const int hh = n >> 6, d = n & 63;
                    if (mode == 1) {
                        writeA3(d0 + ((size_t)(bb * Hn + hh) * Sn + s) * D3n + 3 * d, v0, v1);
                    } else if (mode == 2) {
                        writeB3(d0 + ((size_t)(bb * Hn + hh) * Sn + s) * D3n + 3 * d, v0, v1);
                    } else {
                        u16 h0, l0, h1, l1; split2(v0, h0, l0); split2(v1, h1, l1);
                        const size_t ix = ((size_t)(bb * Hn + hh) * Sn + s) * DKn + d;
                        *(u32*)(d0 + ix) = pk(h0, h1);
                        *(u32*)(d1 + ix) = pk(l0, l1);
                    }
                }
            }
        }
    }
}

// ---------------- warp-MMA flash attention ----------------
// grid (16 qtiles, 8 heads, 4 batch), 256 thr (8 warps, 16 q-rows each).
// Q3 [128][192] persistent in smem; loop 32 key-tiles of 64.
// QK: mma over K'=192; softmax streaming (no max; masked -> exp(-30));
// P frags built in-register (hi+lo); PV: 3 mma vs Vhi/Vlo via ldmatrix.trans.
#define EXPM 9.357623e-14f
__global__ void __launch_bounds__(256) attn_mma_kernel(
    const u16* __restrict__ Q3, const u16* __restrict__ K3,
    const u16* __restrict__ Vh, const u16* __restrict__ Vl,
    const int* __restrict__ mask, u16* __restrict__ X3)
{
    extern __shared__ char smem[];
    char* Qs = smem;                 // 128 x 400B = 51200
    char* Ks = smem + 51200;         // 64 x 400B  = 25600
    char* Vhs = smem + 76800;        // 64 x 144B  = 9216
    char* Vls = smem + 86016;        // 64 x 144B  = 9216  (total 95232)
    const u32 vh_base = smem_u32(Vhs), vl_base = smem_u32(Vls);

    const int tid = threadIdx.x, w = tid >> 5, lane = tid & 31;
    const int qd = lane >> 2, qc = lane & 3;
    const int qt = blockIdx.x, h = blockIdx.y, b = blockIdx.z;
    const int q0 = qt * 128;
    const size_t bh = (size_t)b * Hn + h;

    const u16* Qg = Q3 + (bh * Sn + q0) * D3n;
    const u16* Kg = K3 + bh * Sn * D3n;
    const u16* Vhg = Vh + bh * Sn * DKn;
    const u16* Vlg = Vl + bh * Sn * DKn;

    for (int c = tid; c < 3072; c += 256) {   // Q tile: 128 rows x 24 chunks
        const int row = c / 24, col = c % 24;
        *(uint4*)(Qs + row * 400 + col * 16) = *(const uint4*)(Qg + (size_t)row * D3n + col * 8);
    }

    float O[8][4];
    #pragma unroll
    for (int i = 0; i < 8; i++)
        #pragma unroll
        for (int j = 0; j < 4; j++) O[i][j] = 0.0f;
    float rs0 = 0.0f, rs1 = 0.0f;

    const int qrow0 = q0 + w * 16 + qd;
    const int* mrow0 = mask + ((size_t)b * Sn + qrow0) * Sn;
    const int* mrow1 = mrow0 + 8 * Sn;

    for (int kt = 0; kt < 32; kt++) {
        const int k0 = kt * 64;
        __syncthreads();
        for (int c = tid; c < 1536; c += 256) {   // K tile: 64 x 24 chunks
            const int row = c / 24, col = c % 24;
            *(uint4*)(Ks + row * 400 + col * 16) =
                *(const uint4*)(Kg + (size_t)(k0 + row) * D3n + col * 8);
        }
        for (int c = tid; c < 512; c += 256) {    // V tiles: 64 x 8 chunks
            const int row = c >> 3, col = c & 7;
            *(uint4*)(Vhs + row * 144 + col * 16) =
                *(const uint4*)(Vhg + (size_t)(k0 + row) * DKn + col * 8);
            *(uint4*)(Vls + row * 144 + col * 16) =
                *(const uint4*)(Vlg + (size_t)(k0 + row) * DKn + col * 8);
        }
        __syncthreads();

        // S = Q K^T over K'=192
        float S[8][4];
        #pragma unroll
        for (int i = 0; i < 8; i++)
            #pragma unroll
            for (int j = 0; j < 4; j++) S[i][j] = 0.0f;
        #pragma unroll
        for (int j = 0; j < 12; j++) {
            u32 a[4];
            const char* p = Qs + (w * 16 + qd) * 400 + j * 32 + qc * 4;
            a[0] = *(const u32*)p;
            a[1] = *(const u32*)(p + 8 * 400);
            a[2] = *(const u32*)(p + 16);
            a[3] = *(const u32*)(p + 8 * 400 + 16);
            #pragma unroll
            for (int fn = 0; fn < 8; fn++) {
                const char* q = Ks + (fn * 8 + qd) * 400 + j * 32 + qc * 4;
                u32 bb[2] = { *(const u32*)q, *(const u32*)(q + 16) };
                mma16816(S[fn], a, bb);
            }
        }

        // softmax + PV per 16-key group
        #pragma unroll
        for (int g = 0; g < 4; g++) {
            const float* f0 = S[2 * g];
            const float* f1 = S[2 * g + 1];
            const int kb = k0 + g * 16;
            const int2 m00 = *(const int2*)(mrow0 + kb + qc * 2);
            const int2 m01 = *(const int2*)(mrow0 + kb + 8 + qc * 2);
            const int2 m10 = *(const int2*)(mrow1 + kb + qc * 2);
            const int2 m11 = *(const int2*)(mrow1 + kb + 8 + qc * 2);
            const float p00 = m00.x ? __expf(f0[0] * 0.125f) : EXPM;
            const float p01 = m00.y ? __expf(f0[1] * 0.125f) : EXPM;
            const float p02 = m10.x ? __expf(f0[2] * 0.125f) : EXPM;
            const float p03 = m10.y ? __expf(f0[3] * 0.125f) : EXPM;
            const float p10 = m01.x ? __expf(f1[0] * 0.125f) : EXPM;
            const float p11 = m01.y ? __expf(f1[1] * 0.125f) : EXPM;
            const float p12 = m11.x ? __expf(f1[2] * 0.125f) : EXPM;
            const float p13 = m11.y ? __expf(f1[3] * 0.125f) : EXPM;
            rs0 += (p00 + p01) + (p10 + p11);
            rs1 += (p02 + p03) + (p12 + p13);

            u16 h00, l00, h01, l01, h02, l02, h03, l03;
            u16 h10, l10, h11, l11, h12, l12, h13, l13;
            split2(p00, h00, l00); split2(p01, h01, l01);
            split2(p02, h02, l02); split2(p03, h03, l03);
            split2(p10, h10, l10); split2(p11, h11, l11);
            split2(p12, h12, l12); split2(p13, h13, l13);
            u32 pa[4] = { pk(h00, h01), pk(h02, h03), pk(h10, h11), pk(h12, h13) };
            u32 pl[4] = { pk(l00, l01), pk(l02, l03), pk(l10, l11), pk(l12, l13) };

            u32 vhf[8][2];
            const u32 rowoff = (u32)((g * 16 + (lane & 15)) * 144);
            #pragma unroll
            for (int dn = 0; dn < 8; dn++)
                ldm_x2_trans(vhf[dn][0], vhf[dn][1], vh_base + rowoff + dn * 16);
            #pragma unroll
            for (int dn = 0; dn < 8; dn++) mma16816(O[dn], pa, vhf[dn]);
            #pragma unroll
            for (int dn = 0; dn < 8; dn++) {
                u32 vlf[2];
                ldm_x2_trans(vlf[0], vlf[1], vl_base + rowoff + dn * 16);
                mma16816(O[dn], pa, vlf);
            }
            #pragma unroll
            for (int dn = 0; dn < 8; dn++) mma16816(O[dn], pl, vhf[dn]);
        }
    }

    rs0 += __shfl_xor_sync(0xffffffffu, rs0, 1);
    rs0 += __shfl_xor_sync(0xffffffffu, rs0, 2);
    rs1 += __shfl_xor_sync(0xffffffffu, rs1, 1);
    rs1 += __shfl_xor_sync(0xffffffffu, rs1, 2);
    const float inv0 = 1.0f / rs0, inv1 = 1.0f / rs1;

    const int mg0 = b * Sn + qrow0;
    #pragma unroll
    for (int dn = 0; dn < 8; dn++) {
        const int d = dn * 8 + qc * 2;
        writeA3(X3 + ((size_t)mg0 * K3n + 3 * (h * DKn + d)),
                O[dn][0] * inv0, O[dn][1] * inv0);
        writeA3(X3 + ((size_t)(mg0 + 8) * K3n + 3 * (h * DKn + d)),
                O[dn][2] * inv1, O[dn][3] * inv1);
    }
}

// ---------------- host ----------------
extern "C" void kernel_launch(void* const* d_in, const int* in_sizes, int n_in,
                              void* d_out, int out_size)
{
    const float* query = (const float*)d_in[0];
    const float* key   = (const float*)d_in[1];
    const float* value = (const float*)d_in[2];
    const int*   mask  = (const int*)  d_in[3];
    const float* W[4]  = {(const float*)d_in[4], (const float*)d_in[6],
                          (const float*)d_in[8], (const float*)d_in[10]};
    const float* bias[4] = {(const float*)d_in[5], (const float*)d_in[7],
                            (const float*)d_in[9], (const float*)d_in[11]};
    float* out = (float*)d_out;

    u16 *in3, *w3, *q3, *k3, *vhi, *vlo, *x3;
    cudaGetSymbolAddress((void**)&in3, g_in3);
    cudaGetSymbolAddress((void**)&w3,  g_w3);
    cudaGetSymbolAddress((void**)&q3,  g_q3);
    cudaGetSymbolAddress((void**)&k3,  g_k3);
    cudaGetSymbolAddress((void**)&vhi, g_vhi);
    cudaGetSymbolAddress((void**)&vlo, g_vlo);
    cudaGetSymbolAddress((void**)&x3,  g_x3);

    const int GEMM_SMEM = 2 * 20480;       // 40 KB
    const int ATTN_SMEM = 95232;
    cudaFuncSetAttribute(gemm_mma_kernel, cudaFuncAttributeMaxDynamicSharedMemorySize, GEMM_SMEM);
    cudaFuncSetAttribute(attn_mma_kernel, cudaFuncAttributeMaxDynamicSharedMemorySize, ATTN_SMEM);

    const size_t INSZ = (size_t)MROWS * K3n;
    const size_t WSZ  = (size_t)DMn * K3n;
    convert_kernel<<<2048, 256>>>(query, in3 + 0 * INSZ, MROWS, 0);
    convert_kernel<<<2048, 256>>>(key,   in3 + 1 * INSZ, MROWS, 0);
    convert_kernel<<<2048, 256>>>(value, in3 + 2 * INSZ, MROWS, 0);
    for (int i = 0; i < 4; i++)
        convert_kernel<<<512, 256>>>(W[i], w3 + (size_t)i * WSZ, DMn, 1);

    dim3 gg(MROWS / 128, DMn / 128);   // 64 x 4
    gemm_mma_kernel<<<gg, 256, GEMM_SMEM>>>(in3 + 0 * INSZ, w3 + 0 * WSZ, bias[0], 1,
                                            nullptr, q3, nullptr);
    gemm_mma_kernel<<<gg, 256, GEMM_SMEM>>>(in3 + 1 * INSZ, w3 + 1 * WSZ, bias[1], 2,
                                            nullptr, k3, nullptr);
    gemm_mma_kernel<<<gg, 256, GEMM_SMEM>>>(in3 + 2 * INSZ, w3 + 2 * WSZ, bias[2], 3,
                                            nullptr, vhi, vlo);

    dim3 ag(Sn / 128, Hn, Bn);         // 16 x 8 x 4
    attn_mma_kernel<<<ag, 256, ATTN_SMEM>>>(q3, k3, vhi, vlo, mask, x3);

    gemm_mma_kernel<<<gg, 256, GEMM_SMEM>>>(x3, w3 + 3 * WSZ, bias[3], 0,
                                            out, nullptr, nullptr);
}

// round 6
// speedup vs baseline: 3.3332x; 1.6604x over previous
#include <cuda_runtime.h>
#include <cuda_fp16.h>
#include <cstdint>
#include <math.h>

#define Bn 4
#define Sn 2048
#define DMn 512
#define Hn 8
#define DKn 64
#define BHn (Bn * Hn)             // 32
#define MROWS (Bn * Sn)           // 8192
#define K2n (2 * DMn)             // 1024
#define D2n (2 * DKn)             // 128

typedef unsigned short u16;
typedef unsigned int u32;

// ---------------- scratch (device globals; allocation-free) ----------------
__device__ u16 g_in2[3][MROWS * K2n];        // q/k/v inputs, A-pattern [h,l]
__device__ u16 g_w2[4][DMn * K2n];           // weights, B-pattern [h,h]
__device__ u16 g_q2[BHn * Sn * D2n];         // Q proj, A-pattern  [bh][s][128]
__device__ u16 g_k2[BHn * Sn * D2n];         // K proj, B-pattern  [bh][s][128]
__device__ u16 g_vh[BHn * Sn * DKn];         // V proj, single fp16 [bh][s][64]
__device__ u16 g_x2[MROWS * K2n];            // attn out, A-pattern [m][1024]

// ---------------- helpers ----------------
__device__ __forceinline__ u16 h16(float v) { return __half_as_ushort(__float2half_rn(v)); }
__device__ __forceinline__ void split2h(float v, u16& h, u16& l) {
    __half hh = __float2half_rn(v);
    h = __half_as_ushort(hh);
    l = h16(v - __half2float(hh));
}
__device__ __forceinline__ u32 pk(u16 lo, u16 hi) { return (u32)lo | ((u32)hi << 16); }

__device__ __forceinline__ void mma16816(float* c, const u32* a, const u32* b) {
    asm volatile(
        "mma.sync.aligned.m16n8k16.row.col.f32.f16.f16.f32 "
        "{%0,%1,%2,%3},{%4,%5,%6,%7},{%8,%9},{%0,%1,%2,%3};"
        : "+f"(c[0]), "+f"(c[1]), "+f"(c[2]), "+f"(c[3])
        : "r"(a[0]), "r"(a[1]), "r"(a[2]), "r"(a[3]), "r"(b[0]), "r"(b[1]));
}
__device__ __forceinline__ void ldm_x2_trans(u32& r0, u32& r1, u32 addr) {
    asm volatile("ldmatrix.sync.aligned.m8n8.x2.trans.shared.b16 {%0,%1}, [%2];"
                 : "=r"(r0), "=r"(r1) : "r"(addr));
}
__device__ __forceinline__ u32 smem_u32(const void* p) {
    u32 a;
    asm("{ .reg .u64 t; cvta.to.shared.u64 t, %1; cvt.u32.u64 %0, t; }" : "=r"(a) : "l"(p));
    return a;
}
__device__ __forceinline__ void cpa16(u32 dst, const void* src) {
    asm volatile("cp.async.cg.shared.global [%0], [%1], 16;" :: "r"(dst), "l"(src));
}
#define CP_COMMIT() asm volatile("cp.async.commit_group;" ::: "memory")
#define CP_WAIT1() asm volatile("cp.async.wait_group 1;" ::: "memory")
#define CP_WAIT0() asm volatile("cp.async.wait_group 0;" ::: "memory")

__device__ __forceinline__ void writeA2(u16* p, float v0, float v1) {
    u16 h0, l0, h1, l1; split2h(v0, h0, l0); split2h(v1, h1, l1);
    u32* q = (u32*)p;
    q[0] = pk(h0, l0); q[1] = pk(h1, l1);
}
__device__ __forceinline__ void writeB2(u16* p, float v0, float v1) {
    const u16 h0 = h16(v0), h1 = h16(v1);
    u32* q = (u32*)p;
    q[0] = pk(h0, h0); q[1] = pk(h1, h1);
}

// ---------------- convert: fp32 [rows][512] -> fp16 pair [rows][1024] ----------------
__global__ void __launch_bounds__(256) convert_kernel(
    const float* __restrict__ src, u16* __restrict__ dst, int rows, int bpat)
{
    const int n = rows * 256;   // pairs of k
    for (int i = blockIdx.x * 256 + threadIdx.x; i < n; i += gridDim.x * 256) {
        const int m = i >> 8, kp = i & 255;
        const float2 v = *(const float2*)(src + (size_t)m * DMn + kp * 2);
        u16* p = dst + (size_t)m * K2n + kp * 4;
        if (bpat) writeB2(p, v.x, v.y);
        else      writeA2(p, v.x, v.y);
    }
}

// ---------------- warp-MMA GEMM: C = A2 @ W2^T + bias ----------------
// A2 [8192][1024], W2 [512][1024] (fp16 pair slots). CTA 128x128, slot-step 32,
// 256 thr (8 warps, 4x2), warp tile 32x64, double-buffered cp.async.
// mode 0: fp32 out[m][512]   mode 1: Q2 A-pattern   mode 2: K2 B-pattern
// mode 3: V fp16 plane [bh][s][64]
__global__ void __launch_bounds__(256) gemm_mma_kernel(
    const u16* __restrict__ A2, const u16* __restrict__ W2,
    const float* __restrict__ bias, int mode, float* __restrict__ outF,
    u16* __restrict__ d0)
{
    extern __shared__ char smem[];
    const u32 sbase = smem_u32(smem);
    const int tid = threadIdx.x, w = tid >> 5, lane = tid & 31;
    const int wm = w >> 1, wn = w & 1;
    const int qd = lane >> 2, qc = lane & 3;
    const int m0 = blockIdx.x * 128, n0 = blockIdx.y * 128;

    float acc[2][8][4];
    #pragma unroll
    for (int i = 0; i < 2; i++)
        #pragma unroll
        for (int j = 0; j < 8; j++)
            #pragma unroll
            for (int k = 0; k < 4; k++) acc[i][j][k] = 0.0f;

    auto issue = [&](int stage, int k0) {
        #pragma unroll
        for (int i = 0; i < 4; i++) {
            const int c = tid + i * 256;          // 0..1023
            const int isB = c >> 9;
            const int cc = c & 511;
            const int row = cc >> 2, col = cc & 3;
            const u32 dst = sbase + stage * 20480 + isB * 10240 + row * 80 + col * 16;
            const u16* src = isB ? (W2 + (size_t)(n0 + row) * K2n + k0 + col * 8)
                                 : (A2 + (size_t)(m0 + row) * K2n + k0 + col * 8);
            cpa16(dst, src);
        }
        CP_COMMIT();
    };

    issue(0, 0);
    int buf = 0;
    for (int it = 0; it < 32; it++) {
        if (it + 1 < 32) { issue(buf ^ 1, (it + 1) * 32); CP_WAIT1(); }
        else             { CP_WAIT0(); }
        __syncthreads();
        const char* As = smem + buf * 20480;
        const char* Bs = As + 10240;
        #pragma unroll
        for (int j = 0; j < 2; j++) {
            u32 a[2][4];
            #pragma unroll
            for (int fm = 0; fm < 2; fm++) {
                const char* p = As + (wm * 32 + fm * 16 + qd) * 80 + j * 32 + qc * 4;
                a[fm][0] = *(const u32*)p;
                a[fm][1] = *(const u32*)(p + 8 * 80);
                a[fm][2] = *(const u32*)(p + 16);
                a[fm][3] = *(const u32*)(p + 8 * 80 + 16);
            }
            #pragma unroll
            for (int fn = 0; fn < 8; fn++) {
                const char* q = Bs + (wn * 64 + fn * 8 + qd) * 80 + j * 32 + qc * 4;
                u32 b[2] = { *(const u32*)q, *(const u32*)(q + 16) };
                mma16816(acc[0][fn], a[0], b);
                mma16816(acc[1][fn], a[1], b);
            }
        }
        __syncthreads();
        buf ^= 1;
    }

    // epilogue
    #pragma unroll
    for (int fm = 0; fm < 2; fm++) {
        #pragma unroll
        for (int fn = 0; fn < 8; fn++) {
            const int mbase = m0 + wm * 32 + fm * 16 + qd;
            const int n = n0 + wn * 64 + fn * 8 + qc * 2;
            const float b0 = bias[n], b1 = bias[n + 1];
            #pragma unroll
            for (int half = 0; half < 2; half++) {
                const int m = mbase + half * 8;
                const float v0 = acc[fm][fn][half * 2 + 0] + b0;
                const float v1 = acc[fm][fn][half * 2 + 1] + b1;
                if (mode == 0) {
                    *(float2*)(outF + (size_t)m * DMn + n) = make_float2(v0, v1);
                } else {
                    const int bb = m >> 11, s = m & 2047;
                    const int hh = n >> 6, d = n & 63;
                    if (mode == 1) {
                        writeA2(d0 + ((size_t)(bb * Hn + hh) * Sn + s) * D2n + 2 * d, v0, v1);
                    } else if (mode == 2) {
                        writeB2(d0 + ((size_t)(bb * Hn + hh) * Sn + s) * D2n + 2 * d, v0, v1);
                    } else {
                        const size_t ix = ((size_t)(bb * Hn + hh) * Sn + s) * DKn + d;
                        *(u32*)(d0 + ix) = pk(h16(v0), h16(v1));
                    }
                }
            }
        }
    }
}

// ---------------- warp-MMA flash attention (fp16, one-sided split) ----------------
// grid (16 qtiles, 8 heads, 4 batch), 256 thr (8 warps, 16 q-rows each).
// Q2 [128][128 slots] persistent; 32 key-tiles of 64, K/V double-buffered cp.async.
// QK over K'=128; streaming softmax (no max; masked -> exp(-30));
// PV: P split hi/lo in-register, V single fp16 plane -> 2 mma per fragment.
#define EXPM 9.357623e-14f
__global__ void __launch_bounds__(256) attn_mma_kernel(
    const u16* __restrict__ Q2, const u16* __restrict__ K2,
    const u16* __restrict__ Vh, const int* __restrict__ mask,
    u16* __restrict__ X2)
{
    extern __shared__ char smem[];
    char* Qs = smem;                       // 128 x 272B = 34816
    char* Ks = smem + 34816;               // 2 stages x 64 x 272B = 34816
    char* Vs = smem + 69632;               // 2 stages x 64 x 144B = 18432 (total 88064)
    const u32 ks_base = smem_u32(Ks), vs_base = smem_u32(Vs);

    const int tid = threadIdx.x, w = tid >> 5, lane = tid & 31;
    const int qd = lane >> 2, qc = lane & 3;
    const int qt = blockIdx.x, h = blockIdx.y, b = blockIdx.z;
    const int q0 = qt * 128;
    const size_t bh = (size_t)b * Hn + h;

    const u16* Qg = Q2 + (bh * Sn + q0) * D2n;
    const u16* Kg = K2 + bh * Sn * D2n;
    const u16* Vg = Vh + bh * Sn * DKn;

    for (int c = tid; c < 2048; c += 256) {   // Q tile: 128 rows x 16 chunks
        const int row = c >> 4, col = c & 15;
        *(uint4*)(Qs + row * 272 + col * 16) = *(const uint4*)(Qg + (size_t)row * D2n + col * 8);
    }

    auto issue_kv = [&](int stage, int k0) {
        #pragma unroll
        for (int i = 0; i < 4; i++) {          // K: 64 rows x 16 chunks
            const int c = tid + i * 256;
            const int row = c >> 4, col = c & 15;
            cpa16(ks_base + stage * 17408 + row * 272 + col * 16,
                  Kg + (size_t)(k0 + row) * D2n + col * 8);
        }
        #pragma unroll
        for (int i = 0; i < 2; i++) {          // V: 64 rows x 8 chunks
            const int c = tid + i * 256;
            const int row = c >> 3, col = c & 7;
            cpa16(vs_base + stage * 9216 + row * 144 + col * 16,
                  Vg + (size_t)(k0 + row) * DKn + col * 8);
        }
        CP_COMMIT();
    };

    float O[8][4];
    #pragma unroll
    for (int i = 0; i < 8; i++)
        #pragma unroll
        for (int j = 0; j < 4; j++) O[i][j] = 0.0f;
    float rs0 = 0.0f, rs1 = 0.0f;

    const int qrow0 = q0 + w * 16 + qd;
    const int* mrow0 = mask + ((size_t)b * Sn + qrow0) * Sn;
    const int* mrow1 = mrow0 + 8 * Sn;

    issue_kv(0, 0);
    int buf = 0;
    for (int kt = 0; kt < 32; kt++) {
        const int k0 = kt * 64;
        if (kt + 1 < 32) { issue_kv(buf ^ 1, (kt + 1) * 64); CP_WAIT1(); }
        else             { CP_WAIT0(); }
        __syncthreads();
        const char* Kst = Ks + buf * 17408;
        const u32 vbase = vs_base + buf * 9216;

        // S = Q K^T over K'=128
        float S[8][4];
        #pragma unroll
        for (int i = 0; i < 8; i++)
            #pragma unroll
            for (int j = 0; j < 4; j++) S[i][j] = 0.0f;
        #pragma unroll
        for (int j = 0; j < 8; j++) {
            u32 a[4];
            const char* p = Qs + (w * 16 + qd) * 272 + j * 32 + qc * 4;
            a[0] = *(const u32*)p;
            a[1] = *(const u32*)(p + 8 * 272);
            a[2] = *(const u32*)(p + 16);
            a[3] = *(const u32*)(p + 8 * 272 + 16);
            #pragma unroll
            for (int fn = 0; fn < 8; fn++) {
                const char* q = Kst + (fn * 8 + qd) * 272 + j * 32 + qc * 4;
                u32 bb[2] = { *(const u32*)q, *(const u32*)(q + 16) };
                mma16816(S[fn], a, bb);
            }
        }

        // softmax + PV per 16-key group
        #pragma unroll
        for (int g = 0; g < 4; g++) {
            const float* f0 = S[2 * g];
            const float* f1 = S[2 * g + 1];
            const int kb = k0 + g * 16;
            const int2 m00 = *(const int2*)(mrow0 + kb + qc * 2);
            const int2 m01 = *(const int2*)(mrow0 + kb + 8 + qc * 2);
            const int2 m10 = *(const int2*)(mrow1 + kb + qc * 2);
            const int2 m11 = *(const int2*)(mrow1 + kb + 8 + qc * 2);
            const float p00 = m00.x ? __expf(f0[0] * 0.125f) : EXPM;
            const float p01 = m00.y ? __expf(f0[1] * 0.125f) : EXPM;
            const float p02 = m10.x ? __expf(f0[2] * 0.125f) : EXPM;
            const float p03 = m10.y ? __expf(f0[3] * 0.125f) : EXPM;
            const float p10 = m01.x ? __expf(f1[0] * 0.125f) : EXPM;
            const float p11 = m01.y ? __expf(f1[1] * 0.125f) : EXPM;
            const float p12 = m11.x ? __expf(f1[2] * 0.125f) : EXPM;
            const float p13 = m11.y ? __expf(f1[3] * 0.125f) : EXPM;
            rs0 += (p00 + p01) + (p10 + p11);
            rs1 += (p02 + p03) + (p12 + p13);

            u16 h00, l00, h01, l01, h02, l02, h03, l03;
            u16 h10, l10, h11, l11, h12, l12, h13, l13;
            split2h(p00, h00, l00); split2h(p01, h01, l01);
            split2h(p02, h02, l02); split2h(p03, h03, l03);
            split2h(p10, h10, l10); split2h(p11, h11, l11);
            split2h(p12, h12, l12); split2h(p13, h13, l13);
            u32 pa[4] = { pk(h00, h01), pk(h02, h03), pk(h10, h11), pk(h12, h13) };
            u32 pl[4] = { pk(l00, l01), pk(l02, l03), pk(l10, l11), pk(l12, l13) };

            const u32 rowoff = vbase + (u32)((g * 16 + (lane & 15)) * 144);
            #pragma unroll
            for (int dn = 0; dn < 8; dn++) {
                u32 vf[2];
                ldm_x2_trans(vf[0], vf[1], rowoff + dn * 16);
                mma16816(O[dn], pa, vf);
                mma16816(O[dn], pl, vf);
            }
        }
        __syncthreads();
        buf ^= 1;
    }

    rs0 += __shfl_xor_sync(0xffffffffu, rs0, 1);
    rs0 += __shfl_xor_sync(0xffffffffu, rs0, 2);
    rs1 += __shfl_xor_sync(0xffffffffu, rs1, 1);
    rs1 += __shfl_xor_sync(0xffffffffu, rs1, 2);
    const float inv0 = 1.0f / rs0, inv1 = 1.0f / rs1;

    const int mg0 = b * Sn + qrow0;
    #pragma unroll
    for (int dn = 0; dn < 8; dn++) {
        const int d = dn * 8 + qc * 2;
        writeA2(X2 + ((size_t)mg0 * K2n + 2 * (h * DKn + d)),
                O[dn][0] * inv0, O[dn][1] * inv0);
        writeA2(X2 + ((size_t)(mg0 + 8) * K2n + 2 * (h * DKn + d)),
                O[dn][2] * inv1, O[dn][3] * inv1);
    }
}

// ---------------- host ----------------
extern "C" void kernel_launch(void* const* d_in, const int* in_sizes, int n_in,
                              void* d_out, int out_size)
{
    const float* query = (const float*)d_in[0];
    const float* key   = (const float*)d_in[1];
    const float* value = (const float*)d_in[2];
    const int*   mask  = (const int*)  d_in[3];
    const float* W[4]  = {(const float*)d_in[4], (const float*)d_in[6],
                          (const float*)d_in[8], (const float*)d_in[10]};
    const float* bias[4] = {(const float*)d_in[5], (const float*)d_in[7],
                            (const float*)d_in[9], (const float*)d_in[11]};
    float* out = (float*)d_out;

    u16 *in2, *w2, *q2, *k2, *vh, *x2;
    cudaGetSymbolAddress((void**)&in2, g_in2);
    cudaGetSymbolAddress((void**)&w2,  g_w2);
    cudaGetSymbolAddress((void**)&q2,  g_q2);
    cudaGetSymbolAddress((void**)&k2,  g_k2);
    cudaGetSymbolAddress((void**)&vh,  g_vh);
    cudaGetSymbolAddress((void**)&x2,  g_x2);

    const int GEMM_SMEM = 2 * 20480;       // 40 KB
    const int ATTN_SMEM = 88064;
    cudaFuncSetAttribute(gemm_mma_kernel, cudaFuncAttributeMaxDynamicSharedMemorySize, GEMM_SMEM);
    cudaFuncSetAttribute(attn_mma_kernel, cudaFuncAttributeMaxDynamicSharedMemorySize, ATTN_SMEM);

    const size_t INSZ = (size_t)MROWS * K2n;
    const size_t WSZ  = (size_t)DMn * K2n;
    convert_kernel<<<2048, 256>>>(query, in2 + 0 * INSZ, MROWS, 0);
    convert_kernel<<<2048, 256>>>(key,   in2 + 1 * INSZ, MROWS, 0);
    convert_kernel<<<2048, 256>>>(value, in2 + 2 * INSZ, MROWS, 0);
    for (int i = 0; i < 4; i++)
        convert_kernel<<<512, 256>>>(W[i], w2 + (size_t)i * WSZ, DMn, 1);

    dim3 gg(MROWS / 128, DMn / 128);   // 64 x 4
    gemm_mma_kernel<<<gg, 256, GEMM_SMEM>>>(in2 + 0 * INSZ, w2 + 0 * WSZ, bias[0], 1, nullptr, q2);
    gemm_mma_kernel<<<gg, 256, GEMM_SMEM>>>(in2 + 1 * INSZ, w2 + 1 * WSZ, bias[1], 2, nullptr, k2);
    gemm_mma_kernel<<<gg, 256, GEMM_SMEM>>>(in2 + 2 * INSZ, w2 + 2 * WSZ, bias[2], 3, nullptr, vh);

    dim3 ag(Sn / 128, Hn, Bn);         // 16 x 8 x 4
    attn_mma_kernel<<<ag, 256, ATTN_SMEM>>>(q2, k2, vh, mask, x2);

    gemm_mma_kernel<<<gg, 256, GEMM_SMEM>>>(x2, w2 + 3 * WSZ, bias[3], 0, out, nullptr);
}

// round 11
// speedup vs baseline: 3.3935x; 1.0181x over previous
#include <cuda_runtime.h>
#include <cuda_fp16.h>
#include <cstdint>
#include <math.h>

#define Bn 4
#define Sn 2048
#define DMn 512
#define Hn 8
#define DKn 64
#define BHn (Bn * Hn)             // 32
#define MROWS (Bn * Sn)           // 8192
#define K2n (2 * DMn)             // 1024
#define D2n (2 * DKn)             // 128
#define SW32 (Sn / 32)            // 64
#define MASKN (Bn * Sn * Sn)      // 16777216

typedef unsigned short u16;
typedef unsigned int u32;

// ---------------- scratch (device globals; allocation-free) ----------------
__device__ u16 g_in2[3][MROWS * K2n];        // q/k/v inputs, A-pattern [h,l]
__device__ u16 g_w2[4][DMn * K2n];           // weights, B-pattern [h,h]
__device__ u16 g_q2[BHn * Sn * D2n];         // Q proj, A-pattern  [bh][s][128]
__device__ u16 g_k2[BHn * Sn * D2n];         // K proj, B-pattern  [bh][s][128]
__device__ u16 g_vh[BHn * Sn * DKn];         // V proj, single fp16 [bh][s][64]
__device__ u16 g_x2[MROWS * K2n];            // attn out, A-pattern [m][1024]
__device__ u32 g_mbits[Bn * Sn * SW32];      // bit-packed mask

// ---------------- helpers ----------------
__device__ __forceinline__ u16 h16(float v) { return __half_as_ushort(__float2half_rn(v)); }
__device__ __forceinline__ void split2h(float v, u16& h, u16& l) {
    __half hh = __float2half_rn(v);
    h = __half_as_ushort(hh);
    l = h16(v - __half2float(hh));
}
__device__ __forceinline__ u32 pk(u16 lo, u16 hi) { return (u32)lo | ((u32)hi << 16); }

__device__ __forceinline__ void mma16816(float* c, const u32* a, const u32* b) {
    asm volatile(
        "mma.sync.aligned.m16n8k16.row.col.f32.f16.f16.f32 "
        "{%0,%1,%2,%3},{%4,%5,%6,%7},{%8,%9},{%0,%1,%2,%3};"
        : "+f"(c[0]), "+f"(c[1]), "+f"(c[2]), "+f"(c[3])
        : "r"(a[0]), "r"(a[1]), "r"(a[2]), "r"(a[3]), "r"(b[0]), "r"(b[1]));
}
__device__ __forceinline__ void ldm_x2_trans(u32& r0, u32& r1, u32 addr) {
    asm volatile("ldmatrix.sync.aligned.m8n8.x2.trans.shared.b16 {%0,%1}, [%2];"
                 : "=r"(r0), "=r"(r1) : "r"(addr));
}
__device__ __forceinline__ u32 smem_u32(const void* p) {
    u32 a;
    asm("{ .reg .u64 t; cvta.to.shared.u64 t, %1; cvt.u32.u64 %0, t; }" : "=r"(a) : "l"(p));
    return a;
}
__device__ __forceinline__ void cpa16(u32 dst, const void* src) {
    asm volatile("cp.async.cg.shared.global [%0], [%1], 16;" :: "r"(dst), "l"(src));
}
#define CP_COMMIT() asm volatile("cp.async.commit_group;" ::: "memory")
#define CP_WAIT1() asm volatile("cp.async.wait_group 1;" ::: "memory")
#define CP_WAIT0() asm volatile("cp.async.wait_group 0;" ::: "memory")

__device__ __forceinline__ void writeA2(u16* p, float v0, float v1) {
    u16 h0, l0, h1, l1; split2h(v0, h0, l0); split2h(v1, h1, l1);
    u32* q = (u32*)p;
    q[0] = pk(h0, l0); q[1] = pk(h1, l1);
}
__device__ __forceinline__ void writeB2(u16* p, float v0, float v1) {
    const u16 h0 = h16(v0), h1 = h16(v1);
    u32* q = (u32*)p;
    q[0] = pk(h0, h0); q[1] = pk(h1, h1);
}

// ---------------- mask bit-pack: int32[16.8M] -> u32 bitmask ----------------
// grid MUST cover all MASKN elements: MASKN/256 blocks x 256 threads, 1 elt/thread.
__global__ void __launch_bounds__(256) pack_mask_kernel(
    const int* __restrict__ mask, u32* __restrict__ bits)
{
    const int i = blockIdx.x * 256 + threadIdx.x;
    const u32 w = __ballot_sync(0xffffffffu, mask[i] != 0);
    if ((threadIdx.x & 31) == 0) bits[i >> 5] = w;
}

// ---------------- converts ----------------
__global__ void __launch_bounds__(256) convert_in_kernel(
    const float* __restrict__ q, const float* __restrict__ k,
    const float* __restrict__ v, u16* __restrict__ dst)
{
    const float* src = blockIdx.y == 0 ? q : (blockIdx.y == 1 ? k : v);
    u16* d = dst + (size_t)blockIdx.y * MROWS * K2n;
    const int n = MROWS * 256;
    for (int i = blockIdx.x * 256 + threadIdx.x; i < n; i += gridDim.x * 256) {
        const int m = i >> 8, kp = i & 255;
        const float2 val = *(const float2*)(src + (size_t)m * DMn + kp * 2);
        writeA2(d + (size_t)m * K2n + kp * 4, val.x, val.y);
    }
}
__global__ void __launch_bounds__(256) convert_w_kernel(
    const float* __restrict__ src, u16* __restrict__ dst)
{
    const int n = DMn * 256;
    for (int i = blockIdx.x * 256 + threadIdx.x; i < n; i += gridDim.x * 256) {
        const int m = i >> 8, kp = i & 255;
        const float2 v = *(const float2*)(src + (size_t)m * DMn + kp * 2);
        writeB2(dst + (size_t)m * K2n + kp * 4, v.x, v.y);
    }
}

// ---------------- warp-MMA GEMM: C = A2 @ W2^T + bias ----------------
__global__ void __launch_bounds__(256) gemm_mma_kernel(
    const u16* __restrict__ A2, const u16* __restrict__ W2,
    const float* __restrict__ bias, int mode, float* __restrict__ outF,
    u16* __restrict__ d0)
{
    extern __shared__ char smem[];
    const u32 sbase = smem_u32(smem);
    const int tid = threadIdx.x, w = tid >> 5, lane = tid & 31;
    const int wm = w >> 1, wn = w & 1;
    const int qd = lane >> 2, qc = lane & 3;
    const int m0 = blockIdx.x * 128, n0 = blockIdx.y * 128;

    float acc[2][8][4];
    #pragma unroll
    for (int i = 0; i < 2; i++)
        #pragma unroll
        for (int j = 0; j < 8; j++)
            #pragma unroll
            for (int k = 0; k < 4; k++) acc[i][j][k] = 0.0f;

    auto issue = [&](int stage, int k0) {
        #pragma unroll
        for (int i = 0; i < 4; i++) {
            const int c = tid + i * 256;
            const int isB = c >> 9;
            const int cc = c & 511;
            const int row = cc >> 2, col = cc & 3;
            const u32 dst = sbase + stage * 20480 + isB * 10240 + row * 80 + col * 16;
            const u16* src = isB ? (W2 + (size_t)(n0 + row) * K2n + k0 + col * 8)
                                 : (A2 + (size_t)(m0 + row) * K2n + k0 + col * 8);
            cpa16(dst, src);
        }
        CP_COMMIT();
    };

    issue(0, 0);
    int buf = 0;
    for (int it = 0; it < 32; it++) {
        if (it + 1 < 32) { issue(buf ^ 1, (it + 1) * 32); CP_WAIT1(); }
        else             { CP_WAIT0(); }
        __syncthreads();
        const char* As = smem + buf * 20480;
        const char* Bs = As + 10240;
        #pragma unroll
        for (int j = 0; j < 2; j++) {
            u32 a[2][4];
            #pragma unroll
            for (int fm = 0; fm < 2; fm++) {
                const char* p = As + (wm * 32 + fm * 16 + qd) * 80 + j * 32 + qc * 4;
                a[fm][0] = *(const u32*)p;
                a[fm][1] = *(const u32*)(p + 8 * 80);
                a[fm][2] = *(const u32*)(p + 16);
                a[fm][3] = *(const u32*)(p + 8 * 80 + 16);
            }
            #pragma unroll
            for (int fn = 0; fn < 8; fn++) {
                const char* q = Bs + (wn * 64 + fn * 8 + qd) * 80 + j * 32 + qc * 4;
                u32 b[2] = { *(const u32*)q, *(const u32*)(q + 16) };
                mma16816(acc[0][fn], a[0], b);
                mma16816(acc[1][fn], a[1], b);
            }
        }
        __syncthreads();
        buf ^= 1;
    }

    #pragma unroll
    for (int fm = 0; fm < 2; fm++) {
        #pragma unroll
        for (int fn = 0; fn < 8; fn++) {
            const int mbase = m0 + wm * 32 + fm * 16 + qd;
            const int n = n0 + wn * 64 + fn * 8 + qc * 2;
            const float b0 = bias[n], b1 = bias[n + 1];
            #pragma unroll
            for (int half = 0; half < 2; half++) {
                const int m = mbase + half * 8;
                const float v0 = acc[fm][fn][half * 2 + 0] + b0;
                const float v1 = acc[fm][fn][half * 2 + 1] + b1;
                if (mode == 0) {
                    *(float2*)(outF + (size_t)m * DMn + n) = make_float2(v0, v1);
                } else {
                    const int bb = m >> 11, s = m & 2047;
                    const int hh = n >> 6, d = n & 63;
                    if (mode == 1) {
                        writeA2(d0 + ((size_t)(bb * Hn + hh) * Sn + s) * D2n + 2 * d, v0, v1);
                    } else if (mode == 2) {
                        writeB2(d0 + ((size_t)(bb * Hn + hh) * Sn + s) * D2n + 2 * d, v0, v1);
                    } else {
                        const size_t ix = ((size_t)(bb * Hn + hh) * Sn + s) * DKn + d;
                        *(u32*)(d0 + ix) = pk(h16(v0), h16(v1));
                    }
                }
            }
        }
    }
}

// ---------------- warp-MMA flash attention (fp16, single-fp16 P, bitmask) ----------------
#define EXPM 9.357623e-14f
__global__ void __launch_bounds__(256) attn_mma_kernel(
    const u16* __restrict__ Q2, const u16* __restrict__ K2,
    const u16* __restrict__ Vh, const u32* __restrict__ Mb,
    u16* __restrict__ X2)
{
    extern __shared__ char smem[];
    char* Qs = smem;                       // 128 x 272B = 34816
    char* Ks = smem + 34816;               // 2 stages x 64 x 272B = 34816
    char* Vs = smem + 69632;               // 2 stages x 64 x 144B = 18432 (total 88064)
    const u32 ks_base = smem_u32(Ks), vs_base = smem_u32(Vs);

    const int tid = threadIdx.x, w = tid >> 5, lane = tid & 31;
    const int qd = lane >> 2, qc = lane & 3;
    const int qt = blockIdx.x, h = blockIdx.y, b = blockIdx.z;
    const int q0 = qt * 128;
    const size_t bh = (size_t)b * Hn + h;

    const u16* Qg = Q2 + (bh * Sn + q0) * D2n;
    const u16* Kg = K2 + bh * Sn * D2n;
    const u16* Vg = Vh + bh * Sn * DKn;

    for (int c = tid; c < 2048; c += 256) {   // Q tile
        const int row = c >> 4, col = c & 15;
        *(uint4*)(Qs + row * 272 + col * 16) = *(const uint4*)(Qg + (size_t)row * D2n + col * 8);
    }

    auto issue_kv = [&](int stage, int k0) {
        #pragma unroll
        for (int i = 0; i < 4; i++) {
            const int c = tid + i * 256;
            const int row = c >> 4, col = c & 15;
            cpa16(ks_base + stage * 17408 + row * 272 + col * 16,
                  Kg + (size_t)(k0 + row) * D2n + col * 8);
        }
        #pragma unroll
        for (int i = 0; i < 2; i++) {
            const int c = tid + i * 256;
            const int row = c >> 3, col = c & 7;
            cpa16(vs_base + stage * 9216 + row * 144 + col * 16,
                  Vg + (size_t)(k0 + row) * DKn + col * 8);
        }
        CP_COMMIT();
    };

    float O[8][4];
    #pragma unroll
    for (int i = 0; i < 8; i++)
        #pragma unroll
        for (int j = 0; j < 4; j++) O[i][j] = 0.0f;
    float rs0 = 0.0f, rs1 = 0.0f;

    const int qrow0 = q0 + w * 16 + qd;
    const u32* mb0 = Mb + ((size_t)b * Sn + qrow0) * SW32;
    const u32* mb1 = mb0 + 8 * SW32;

    issue_kv(0, 0);
    int buf = 0;
    for (int kt = 0; kt < 32; kt++) {
        const int k0 = kt * 64;
        if (kt + 1 < 32) { issue_kv(buf ^ 1, (kt + 1) * 64); CP_WAIT1(); }
        else             { CP_WAIT0(); }
        __syncthreads();
        const char* Kst = Ks + buf * 17408;
        const u32 vbase = vs_base + buf * 9216;

        // mask words for this 64-key window (2 rows x 2 u32)
        const int wix = k0 >> 5;
        const u32 m0a = mb0[wix], m0b = mb0[wix + 1];
        const u32 m1a = mb1[wix], m1b = mb1[wix + 1];

        // S = Q K^T over K'=128
        float S[8][4];
        #pragma unroll
        for (int i = 0; i < 8; i++)
            #pragma unroll
            for (int j = 0; j < 4; j++) S[i][j] = 0.0f;
        #pragma unroll
        for (int j = 0; j < 8; j++) {
            u32 a[4];
            const char* p = Qs + (w * 16 + qd) * 272 + j * 32 + qc * 4;
            a[0] = *(const u32*)p;
            a[1] = *(const u32*)(p + 8 * 272);
            a[2] = *(const u32*)(p + 16);
            a[3] = *(const u32*)(p + 8 * 272 + 16);
            #pragma unroll
            for (int fn = 0; fn < 8; fn++) {
                const char* q = Kst + (fn * 8 + qd) * 272 + j * 32 + qc * 4;
                u32 bb[2] = { *(const u32*)q, *(const u32*)(q + 16) };
                mma16816(S[fn], a, bb);
            }
        }

        // softmax + PV per 16-key group
        #pragma unroll
        for (int g = 0; g < 4; g++) {
            const float* f0 = S[2 * g];
            const float* f1 = S[2 * g + 1];
            const u32 w0 = (g & 2) ? m0b : m0a;
            const u32 w1 = (g & 2) ? m1b : m1a;
            const int sh = ((g & 1) << 4) + qc * 2;
            const float p00 = ((w0 >> (sh + 0)) & 1) ? __expf(f0[0] * 0.125f) : EXPM;
            const float p01 = ((w0 >> (sh + 1)) & 1) ? __expf(f0[1] * 0.125f) : EXPM;
            const float p02 = ((w1 >> (sh + 0)) & 1) ? __expf(f0[2] * 0.125f) : EXPM;
            const float p03 = ((w1 >> (sh + 1)) & 1) ? __expf(f0[3] * 0.125f) : EXPM;
            const float p10 = ((w0 >> (sh + 8)) & 1) ? __expf(f1[0] * 0.125f) : EXPM;
            const float p11 = ((w0 >> (sh + 9)) & 1) ? __expf(f1[1] * 0.125f) : EXPM;
            const float p12 = ((w1 >> (sh + 8)) & 1) ? __expf(f1[2] * 0.125f) : EXPM;
            const float p13 = ((w1 >> (sh + 9)) & 1) ? __expf(f1[3] * 0.125f) : EXPM;
            rs0 += (p00 + p01) + (p10 + p11);
            rs1 += (p02 + p03) + (p12 + p13);

            u32 pa[4] = { pk(h16(p00), h16(p01)), pk(h16(p02), h16(p03)),
                          pk(h16(p10), h16(p11)), pk(h16(p12), h16(p13)) };

            const u32 rowoff = vbase + (u32)((g * 16 + (lane & 15)) * 144);
            #pragma unroll
            for (int dn = 0; dn < 8; dn++) {
                u32 vf[2];
                ldm_x2_trans(vf[0], vf[1], rowoff + dn * 16);
                mma16816(O[dn], pa, vf);
            }
        }
        __syncthreads();
        buf ^= 1;
    }

    rs0 += __shfl_xor_sync(0xffffffffu, rs0, 1);
    rs0 += __shfl_xor_sync(0xffffffffu, rs0, 2);
    rs1 += __shfl_xor_sync(0xffffffffu, rs1, 1);
    rs1 += __shfl_xor_sync(0xffffffffu, rs1, 2);
    const float inv0 = 1.0f / rs0, inv1 = 1.0f / rs1;

    const int mg0 = b * Sn + qrow0;
    #pragma unroll
    for (int dn = 0; dn < 8; dn++) {
        const int d = dn * 8 + qc * 2;
        writeA2(X2 + ((size_t)mg0 * K2n + 2 * (h * DKn + d)),
                O[dn][0] * inv0, O[dn][1] * inv0);
        writeA2(X2 + ((size_t)(mg0 + 8) * K2n + 2 * (h * DKn + d)),
                O[dn][2] * inv1, O[dn][3] * inv1);
    }
}

// ---------------- host ----------------
extern "C" void kernel_launch(void* const* d_in, const int* in_sizes, int n_in,
                              void* d_out, int out_size)
{
    const float* query = (const float*)d_in[0];
    const float* key   = (const float*)d_in[1];
    const float* value = (const float*)d_in[2];
    const int*   mask  = (const int*)  d_in[3];
    const float* W[4]  = {(const float*)d_in[4], (const float*)d_in[6],
                          (const float*)d_in[8], (const float*)d_in[10]};
    const float* bias[4] = {(const float*)d_in[5], (const float*)d_in[7],
                            (const float*)d_in[9], (const float*)d_in[11]};
    float* out = (float*)d_out;

    u16 *in2, *w2, *q2, *k2, *vh, *x2;
    u32 *mb;
    cudaGetSymbolAddress((void**)&in2, g_in2);
    cudaGetSymbolAddress((void**)&w2,  g_w2);
    cudaGetSymbolAddress((void**)&q2,  g_q2);
    cudaGetSymbolAddress((void**)&k2,  g_k2);
    cudaGetSymbolAddress((void**)&vh,  g_vh);
    cudaGetSymbolAddress((void**)&x2,  g_x2);
    cudaGetSymbolAddress((void**)&mb,  g_mbits);

    const int GEMM_SMEM = 2 * 20480;       // 40 KB
    const int ATTN_SMEM = 88064;
    cudaFuncSetAttribute(gemm_mma_kernel, cudaFuncAttributeMaxDynamicSharedMemorySize, GEMM_SMEM);
    cudaFuncSetAttribute(attn_mma_kernel, cudaFuncAttributeMaxDynamicSharedMemorySize, ATTN_SMEM);

    pack_mask_kernel<<<MASKN / 256, 256>>>(mask, mb);   // 65536 blocks: full coverage
    convert_in_kernel<<<dim3(2048, 3), 256>>>(query, key, value, in2);
    const size_t WSZ = (size_t)DMn * K2n;
    for (int i = 0; i < 4; i++)
        convert_w_kernel<<<512, 256>>>(W[i], w2 + (size_t)i * WSZ);

    const size_t INSZ = (size_t)MROWS * K2n;
    dim3 gg(MROWS / 128, DMn / 128);   // 64 x 4
    gemm_mma_kernel<<<gg, 256, GEMM_SMEM>>>(in2 + 0 * INSZ, w2 + 0 * WSZ, bias[0], 1, nullptr, q2);
    gemm_mma_kernel<<<gg, 256, GEMM_SMEM>>>(in2 + 1 * INSZ, w2 + 1 * WSZ, bias[1], 2, nullptr, k2);
    gemm_mma_kernel<<<gg, 256, GEMM_SMEM>>>(in2 + 2 * INSZ, w2 + 2 * WSZ, bias[2], 3, nullptr, vh);

    dim3 ag(Sn / 128, Hn, Bn);         // 16 x 8 x 4
    attn_mma_kernel<<<ag, 256, ATTN_SMEM>>>(q2, k2, vh, mb, x2);

    gemm_mma_kernel<<<gg, 256, GEMM_SMEM>>>(x2, w2 + 3 * WSZ, bias[3], 0, out, nullptr);
}

// round 14
// speedup vs baseline: 3.6867x; 1.0864x over previous
#include <cuda_runtime.h>
#include <cuda_fp16.h>
#include <cstdint>
#include <math.h>

#define Bn 4
#define Sn 2048
#define DMn 512
#define Hn 8
#define DKn 64
#define BHn (Bn * Hn)             // 32
#define MROWS (Bn * Sn)           // 8192
#define K2n (2 * DMn)             // 1024
#define D2n (2 * DKn)             // 128
#define SW32 (Sn / 32)            // 64
#define MASKN (Bn * Sn * Sn)      // 16777216

typedef unsigned short u16;
typedef unsigned int u32;

// ---------------- scratch (device globals; allocation-free) ----------------
__device__ u16 g_in2[3][MROWS * K2n];        // q/k/v inputs, A-pattern [h,l]
__device__ u16 g_w2[4][DMn * K2n];           // weights, B-pattern [h,h]
__device__ u16 g_q2[BHn * Sn * D2n];         // Q proj, A-pattern  [bh][s][128]
__device__ u16 g_k2[BHn * Sn * D2n];         // K proj, B-pattern  [bh][s][128]
__device__ u16 g_vh[BHn * Sn * DKn];         // V proj, single fp16 [bh][s][64]
__device__ u16 g_x2[MROWS * K2n];            // attn out, A-pattern [m][1024]
__device__ u32 g_mbits[Bn * Sn * SW32];      // bit-packed mask

// ---------------- helpers ----------------
__device__ __forceinline__ u16 h16(float v) { return __half_as_ushort(__float2half_rn(v)); }
__device__ __forceinline__ void split2h(float v, u16& h, u16& l) {
    __half hh = __float2half_rn(v);
    h = __half_as_ushort(hh);
    l = h16(v - __half2float(hh));
}
__device__ __forceinline__ u32 pk(u16 lo, u16 hi) { return (u32)lo | ((u32)hi << 16); }

__device__ __forceinline__ void mma16816(float* c, const u32* a, const u32* b) {
    asm volatile(
        "mma.sync.aligned.m16n8k16.row.col.f32.f16.f16.f32 "
        "{%0,%1,%2,%3},{%4,%5,%6,%7},{%8,%9},{%0,%1,%2,%3};"
        : "+f"(c[0]), "+f"(c[1]), "+f"(c[2]), "+f"(c[3])
        : "r"(a[0]), "r"(a[1]), "r"(a[2]), "r"(a[3]), "r"(b[0]), "r"(b[1]));
}
__device__ __forceinline__ void ldm_x4(u32& r0, u32& r1, u32& r2, u32& r3, u32 addr) {
    asm volatile("ldmatrix.sync.aligned.m8n8.x4.shared.b16 {%0,%1,%2,%3}, [%4];"
                 : "=r"(r0), "=r"(r1), "=r"(r2), "=r"(r3) : "r"(addr));
}
__device__ __forceinline__ void ldm_x2_trans(u32& r0, u32& r1, u32 addr) {
    asm volatile("ldmatrix.sync.aligned.m8n8.x2.trans.shared.b16 {%0,%1}, [%2];"
                 : "=r"(r0), "=r"(r1) : "r"(addr));
}
__device__ __forceinline__ u32 smem_u32(const void* p) {
    u32 a;
    asm("{ .reg .u64 t; cvta.to.shared.u64 t, %1; cvt.u32.u64 %0, t; }" : "=r"(a) : "l"(p));
    return a;
}
__device__ __forceinline__ void cpa16(u32 dst, const void* src) {
    asm volatile("cp.async.cg.shared.global [%0], [%1], 16;" :: "r"(dst), "l"(src));
}
#define CP_COMMIT() asm volatile("cp.async.commit_group;" ::: "memory")
#define CP_WAIT1() asm volatile("cp.async.wait_group 1;" ::: "memory")
#define CP_WAIT0() asm volatile("cp.async.wait_group 0;" ::: "memory")

__device__ __forceinline__ void writeA2(u16* p, float v0, float v1) {
    u16 h0, l0, h1, l1; split2h(v0, h0, l0); split2h(v1, h1, l1);
    u32* q = (u32*)p;
    q[0] = pk(h0, l0); q[1] = pk(h1, l1);
}
__device__ __forceinline__ void writeB2(u16* p, float v0, float v1) {
    const u16 h0 = h16(v0), h1 = h16(v1);
    u32* q = (u32*)p;
    q[0] = pk(h0, h0); q[1] = pk(h1, h1);
}

// ---------------- mask bit-pack (full coverage: MASKN/256 blocks) ----------------
__global__ void __launch_bounds__(256) pack_mask_kernel(
    const int* __restrict__ mask, u32* __restrict__ bits)
{
    const int i = blockIdx.x * 256 + threadIdx.x;
    const u32 w = __ballot_sync(0xffffffffu, mask[i] != 0);
    if ((threadIdx.x & 31) == 0) bits[i >> 5] = w;
}

// ---------------- converts ----------------
__global__ void __launch_bounds__(256) convert_in_kernel(
    const float* __restrict__ q, const float* __restrict__ k,
    const float* __restrict__ v, u16* __restrict__ dst)
{
    const float* src = blockIdx.y == 0 ? q : (blockIdx.y == 1 ? k : v);
    u16* d = dst + (size_t)blockIdx.y * MROWS * K2n;
    const int n = MROWS * 256;
    for (int i = blockIdx.x * 256 + threadIdx.x; i < n; i += gridDim.x * 256) {
        const int m = i >> 8, kp = i & 255;
        const float2 val = *(const float2*)(src + (size_t)m * DMn + kp * 2);
        writeA2(d + (size_t)m * K2n + kp * 4, val.x, val.y);
    }
}
__global__ void __launch_bounds__(256) convert_w_kernel(
    const float* __restrict__ w0, const float* __restrict__ w1,
    const float* __restrict__ w2s, const float* __restrict__ w3,
    u16* __restrict__ dst)
{
    const int z = blockIdx.y;
    const float* src = z == 0 ? w0 : (z == 1 ? w1 : (z == 2 ? w2s : w3));
    u16* d = dst + (size_t)z * DMn * K2n;
    const int n = DMn * 256;
    for (int i = blockIdx.x * 256 + threadIdx.x; i < n; i += gridDim.x * 256) {
        const int m = i >> 8, kp = i & 255;
        const float2 v = *(const float2*)(src + (size_t)m * DMn + kp * 2);
        writeB2(d + (size_t)m * K2n + kp * 4, v.x, v.y);
    }
}

// ---------------- shared GEMM body: C = A2 @ W2^T + bias ----------------
// ldmatrix mainloop. smem stage: A 128 rows x 80B, B 128 rows x 80B (20480 B/stage).
__device__ __forceinline__ void gemm_body(
    const u16* __restrict__ A2, const u16* __restrict__ W2,
    const float* __restrict__ bias, int mode, float* __restrict__ outF,
    u16* __restrict__ d0, char* smem, int m0, int n0)
{
    const u32 sbase = smem_u32(smem);
    const int tid = threadIdx.x, w = tid >> 5, lane = tid & 31;
    const int wm = w >> 1, wn = w & 1;
    const int qd = lane >> 2, qc = lane & 3;

    float acc[2][8][4];
    #pragma unroll
    for (int i = 0; i < 2; i++)
        #pragma unroll
        for (int j = 0; j < 8; j++)
            #pragma unroll
            for (int k = 0; k < 4; k++) acc[i][j][k] = 0.0f;

    auto issue = [&](int stage, int k0) {
        #pragma unroll
        for (int i = 0; i < 4; i++) {
            const int c = tid + i * 256;
            const int isB = c >> 9;
            const int cc = c & 511;
            const int row = cc >> 2, col = cc & 3;
            const u32 dst = sbase + stage * 20480 + isB * 10240 + row * 80 + col * 16;
            const u16* src = isB ? (W2 + (size_t)(n0 + row) * K2n + k0 + col * 8)
                                 : (A2 + (size_t)(m0 + row) * K2n + k0 + col * 8);
            cpa16(dst, src);
        }
        CP_COMMIT();
    };

    // ldmatrix lane-address components (constant over loop)
    const u32 a_row = (u32)(lane & 15);
    const u32 a_byte = (u32)((lane >> 4) << 4);
    const u32 b_row = (u32)(((lane >> 4) & 1) * 8 + (lane & 7));
    const u32 b_byte = (u32)(((lane >> 3) & 1) << 4);

    issue(0, 0);
    int buf = 0;
    for (int it = 0; it < 32; it++) {
        if (it + 1 < 32) { issue(buf ^ 1, (it + 1) * 32); CP_WAIT1(); }
        else             { CP_WAIT0(); }
        __syncthreads();
        const u32 sA = sbase + buf * 20480;
        const u32 sB = sA + 10240;
        #pragma unroll
        for (int j = 0; j < 2; j++) {
            u32 a[2][4];
            #pragma unroll
            for (int fm = 0; fm < 2; fm++)
                ldm_x4(a[fm][0], a[fm][1], a[fm][2], a[fm][3],
                       sA + (wm * 32 + fm * 16 + a_row) * 80 + j * 32 + a_byte);
            #pragma unroll
            for (int fp = 0; fp < 4; fp++) {
                u32 b[4];
                ldm_x4(b[0], b[1], b[2], b[3],
                       sB + (wn * 64 + fp * 16 + b_row) * 80 + j * 32 + b_byte);
                mma16816(acc[0][2 * fp + 0], a[0], b);
                mma16816(acc[0][2 * fp + 1], a[0], b + 2);
                mma16816(acc[1][2 * fp + 0], a[1], b);
                mma16816(acc[1][2 * fp + 1], a[1], b + 2);
            }
        }
        __syncthreads();
        buf ^= 1;
    }

    #pragma unroll
    for (int fm = 0; fm < 2; fm++) {
        #pragma unroll
        for (int fn = 0; fn < 8; fn++) {
            const int mbase = m0 + wm * 32 + fm * 16 + qd;
            const int n = n0 + wn * 64 + fn * 8 + qc * 2;
            const float b0 = bias[n], b1 = bias[n + 1];
            #pragma unroll
            for (int half = 0; half < 2; half++) {
                const int m = mbase + half * 8;
                const float v0 = acc[fm][fn][half * 2 + 0] + b0;
                const float v1 = acc[fm][fn][half * 2 + 1] + b1;
                if (mode == 0) {
                    *(float2*)(outF + (size_t)m * DMn + n) = make_float2(v0, v1);
                } else {
                    const int bb = m >> 11, s = m & 2047;
                    const int hh = n >> 6, d = n & 63;
                    if (mode == 1) {
                        writeA2(d0 + ((size_t)(bb * Hn + hh) * Sn + s) * D2n + 2 * d, v0, v1);
                    } else if (mode == 2) {
                        writeB2(d0 + ((size_t)(bb * Hn + hh) * Sn + s) * D2n + 2 * d, v0, v1);
                    } else {
                        const size_t ix = ((size_t)(bb * Hn + hh) * Sn + s) * DKn + d;
                        *(u32*)(d0 + ix) = pk(h16(v0), h16(v1));
                    }
                }
            }
        }
    }
}

// fused Q/K/V projections: grid.z selects which projection
__global__ void __launch_bounds__(256) proj_mma_kernel(
    const u16* __restrict__ A2base, const u16* __restrict__ W2base,
    const float* __restrict__ bq, const float* __restrict__ bk,
    const float* __restrict__ bv,
    u16* __restrict__ q2, u16* __restrict__ k2, u16* __restrict__ vh)
{
    extern __shared__ char smem[];
    const int z = blockIdx.z;
    const u16* A2 = A2base + (size_t)z * MROWS * K2n;
    const u16* W2 = W2base + (size_t)z * DMn * K2n;
    const float* bias = z == 0 ? bq : (z == 1 ? bk : bv);
    u16* d0 = z == 0 ? q2 : (z == 1 ? k2 : vh);
    gemm_body(A2, W2, bias, z + 1, nullptr, d0, smem,
              blockIdx.x * 128, blockIdx.y * 128);
}

// output projection (fp32 out)
__global__ void __launch_bounds__(256) gemm_out_kernel(
    const u16* __restrict__ A2, const u16* __restrict__ W2,
    const float* __restrict__ bias, float* __restrict__ outF)
{
    extern __shared__ char smem[];
    gemm_body(A2, W2, bias, 0, outF, nullptr, smem,
              blockIdx.x * 128, blockIdx.y * 128);
}

// ---------------- warp-MMA flash attention (fp16, single-fp16 P, bitmask) ----------------
#define EXPM 9.357623e-14f
__global__ void __launch_bounds__(256) attn_mma_kernel(
    const u16* __restrict__ Q2, const u16* __restrict__ K2,
    const u16* __restrict__ Vh, const u32* __restrict__ Mb,
    u16* __restrict__ X2)
{
    extern __shared__ char smem[];
    char* Qs = smem;                       // 128 x 272B = 34816
    char* Ks = smem + 34816;               // 2 stages x 64 x 272B = 34816
    char* Vs = smem + 69632;               // 2 stages x 64 x 144B = 18432 (total 88064)
    const u32 qs_base = smem_u32(Qs), ks_base = smem_u32(Ks), vs_base = smem_u32(Vs);

    const int tid = threadIdx.x, w = tid >> 5, lane = tid & 31;
    const int qd = lane >> 2, qc = lane & 3;
    const int qt = blockIdx.x, h = blockIdx.y, b = blockIdx.z;
    const int q0 = qt * 128;
    const size_t bh = (size_t)b * Hn + h;

    const u16* Qg = Q2 + (bh * Sn + q0) * D2n;
    const u16* Kg = K2 + bh * Sn * D2n;
    const u16* Vg = Vh + bh * Sn * DKn;

    for (int c = tid; c < 2048; c += 256) {   // Q tile
        const int row = c >> 4, col = c & 15;
        *(uint4*)(Qs + row * 272 + col * 16) = *(const uint4*)(Qg + (size_t)row * D2n + col * 8);
    }

    auto issue_kv = [&](int stage, int k0) {
        #pragma unroll
        for (int i = 0; i < 4; i++) {
            const int c = tid + i * 256;
            const int row = c >> 4, col = c & 15;
            cpa16(ks_base + stage * 17408 + row * 272 + col * 16,
                  Kg + (size_t)(k0 + row) * D2n + col * 8);
        }
        #pragma unroll
        for (int i = 0; i < 2; i++) {
            const int c = tid + i * 256;
            const int row = c >> 3, col = c & 7;
            cpa16(vs_base + stage * 9216 + row * 144 + col * 16,
                  Vg + (size_t)(k0 + row) * DKn + col * 8);
        }
        CP_COMMIT();
    };

    float O[8][4];
    #pragma unroll
    for (int i = 0; i < 8; i++)
        #pragma unroll
        for (int j = 0; j < 4; j++) O[i][j] = 0.0f;
    float rs0 = 0.0f, rs1 = 0.0f;

    const int qrow0 = q0 + w * 16 + qd;
    const u32* mb0 = Mb + ((size_t)b * Sn + qrow0) * SW32;
    const u32* mb1 = mb0 + 8 * SW32;

    // ldmatrix lane-address components
    const u32 a_row = (u32)(lane & 15);
    const u32 a_byte = (u32)((lane >> 4) << 4);
    const u32 b_row = (u32)(((lane >> 4) & 1) * 8 + (lane & 7));
    const u32 b_byte = (u32)(((lane >> 3) & 1) << 4);

    issue_kv(0, 0);
    int buf = 0;
    for (int kt = 0; kt < 32; kt++) {
        const int k0 = kt * 64;
        if (kt + 1 < 32) { issue_kv(buf ^ 1, (kt + 1) * 64); CP_WAIT1(); }
        else             { CP_WAIT0(); }
        __syncthreads();
        const u32 kst = ks_base + buf * 17408;
        const u32 vbase = vs_base + buf * 9216;

        const int wix = k0 >> 5;
        const u32 m0a = mb0[wix], m0b = mb0[wix + 1];
        const u32 m1a = mb1[wix], m1b = mb1[wix + 1];

        // S = Q K^T over K'=128 (ldmatrix fragments)
        float S[8][4];
        #pragma unroll
        for (int i = 0; i < 8; i++)
            #pragma unroll
            for (int j = 0; j < 4; j++) S[i][j] = 0.0f;
        #pragma unroll
        for (int j = 0; j < 8; j++) {
            u32 a[4];
            ldm_x4(a[0], a[1], a[2], a[3],
                   qs_base + (w * 16 + a_row) * 272 + j * 32 + a_byte);
            #pragma unroll
            for (int fp = 0; fp < 4; fp++) {
                u32 bb[4];
                ldm_x4(bb[0], bb[1], bb[2], bb[3],
                       kst + (fp * 16 + b_row) * 272 + j * 32 + b_byte);
                mma16816(S[2 * fp + 0], a, bb);
                mma16816(S[2 * fp + 1], a, bb + 2);
            }
        }

        // softmax + PV per 16-key group
        #pragma unroll
        for (int g = 0; g < 4; g++) {
            const float* f0 = S[2 * g];
            const float* f1 = S[2 * g + 1];
            const u32 w0 = (g & 2) ? m0b : m0a;
            const u32 w1 = (g & 2) ? m1b : m1a;
            const int sh = ((g & 1) << 4) + qc * 2;
            const float p00 = ((w0 >> (sh + 0)) & 1) ? __expf(f0[0] * 0.125f) : EXPM;
            const float p01 = ((w0 >> (sh + 1)) & 1) ? __expf(f0[1] * 0.125f) : EXPM;
            const float p02 = ((w1 >> (sh + 0)) & 1) ? __expf(f0[2] * 0.125f) : EXPM;
            const float p03 = ((w1 >> (sh + 1)) & 1) ? __expf(f0[3] * 0.125f) : EXPM;
            const float p10 = ((w0 >> (sh + 8)) & 1) ? __expf(f1[0] * 0.125f) : EXPM;
            const float p11 = ((w0 >> (sh + 9)) & 1) ? __expf(f1[1] * 0.125f) : EXPM;
            const float p12 = ((w1 >> (sh + 8)) & 1) ? __expf(f1[2] * 0.125f) : EXPM;
            const float p13 = ((w1 >> (sh + 9)) & 1) ? __expf(f1[3] * 0.125f) : EXPM;
            rs0 += (p00 + p01) + (p10 + p11);
            rs1 += (p02 + p03) + (p12 + p13);

            u32 pa[4] = { pk(h16(p00), h16(p01)), pk(h16(p02), h16(p03)),
                          pk(h16(p10), h16(p11)), pk(h16(p12), h16(p13)) };

            const u32 rowoff = vbase + (u32)((g * 16 + (lane & 15)) * 144);
            #pragma unroll
            for (int dn = 0; dn < 8; dn++) {
                u32 vf[2];
                ldm_x2_trans(vf[0], vf[1], rowoff + dn * 16);
                mma16816(O[dn], pa, vf);
            }
        }
        __syncthreads();
        buf ^= 1;
    }

    rs0 += __shfl_xor_sync(0xffffffffu, rs0, 1);
    rs0 += __shfl_xor_sync(0xffffffffu, rs0, 2);
    rs1 += __shfl_xor_sync(0xffffffffu, rs1, 1);
    rs1 += __shfl_xor_sync(0xffffffffu, rs1, 2);
    const float inv0 = 1.0f / rs0, inv1 = 1.0f / rs1;

    const int mg0 = b * Sn + qrow0;
    #pragma unroll
    for (int dn = 0; dn < 8; dn++) {
        const int d = dn * 8 + qc * 2;
        writeA2(X2 + ((size_t)mg0 * K2n + 2 * (h * DKn + d)),
                O[dn][0] * inv0, O[dn][1] * inv0);
        writeA2(X2 + ((size_t)(mg0 + 8) * K2n + 2 * (h * DKn + d)),
                O[dn][2] * inv1, O[dn][3] * inv1);
    }
}

// ---------------- host ----------------
extern "C" void kernel_launch(void* const* d_in, const int* in_sizes, int n_in,
                              void* d_out, int out_size)
{
    const float* query = (const float*)d_in[0];
    const float* key   = (const float*)d_in[1];
    const float* value = (const float*)d_in[2];
    const int*   mask  = (const int*)  d_in[3];
    const float* W[4]  = {(const float*)d_in[4], (const float*)d_in[6],
                          (const float*)d_in[8], (const float*)d_in[10]};
    const float* bias[4] = {(const float*)d_in[5], (const float*)d_in[7],
                            (const float*)d_in[9], (const float*)d_in[11]};
    float* out = (float*)d_out;

    u16 *in2, *w2, *q2, *k2, *vh, *x2;
    u32 *mb;
    cudaGetSymbolAddress((void**)&in2, g_in2);
    cudaGetSymbolAddress((void**)&w2,  g_w2);
    cudaGetSymbolAddress((void**)&q2,  g_q2);
    cudaGetSymbolAddress((void**)&k2,  g_k2);
    cudaGetSymbolAddress((void**)&vh,  g_vh);
    cudaGetSymbolAddress((void**)&x2,  g_x2);
    cudaGetSymbolAddress((void**)&mb,  g_mbits);

    const int GEMM_SMEM = 2 * 20480;       // 40 KB
    const int ATTN_SMEM = 88064;
    cudaFuncSetAttribute(proj_mma_kernel, cudaFuncAttributeMaxDynamicSharedMemorySize, GEMM_SMEM);
    cudaFuncSetAttribute(gemm_out_kernel, cudaFuncAttributeMaxDynamicSharedMemorySize, GEMM_SMEM);
    cudaFuncSetAttribute(attn_mma_kernel, cudaFuncAttributeMaxDynamicSharedMemorySize, ATTN_SMEM);

    pack_mask_kernel<<<MASKN / 256, 256>>>(mask, mb);
    convert_in_kernel<<<dim3(2048, 3), 256>>>(query, key, value, in2);
    convert_w_kernel<<<dim3(512, 4), 256>>>(W[0], W[1], W[2], W[3], w2);

    dim3 pg(MROWS / 128, DMn / 128, 3);   // 64 x 4 x 3
    proj_mma_kernel<<<pg, 256, GEMM_SMEM>>>(in2, w2, bias[0], bias[1], bias[2], q2, k2, vh);

    dim3 ag(Sn / 128, Hn, Bn);            // 16 x 8 x 4
    attn_mma_kernel<<<ag, 256, ATTN_SMEM>>>(q2, k2, vh, mb, x2);

    dim3 gg(MROWS / 128, DMn / 128);      // 64 x 4
    gemm_out_kernel<<<gg, 256, GEMM_SMEM>>>(x2, w2 + 3 * (size_t)DMn * K2n, bias[3], out);
}